// round 14
// baseline (speedup 1.0000x reference)
#include <cuda_runtime.h>
#include <math.h>
#include <stdint.h>

#define MAX_E     4194304
#define MAX_NOUT  524288
#define CCH       64            // channels
#define CV4       16            // float4 per row
#define CAP       16            // bin slots per segment (P(deg>16)~2e-4 -> overflow kernel)
#define OVF_CAP   262144

// -------- device scratch (no dynamic allocation allowed) --------
// Zero-initialized at module load; k_pool / k_overflow restore the zero state
// every run, so no zeroing kernel is needed (state is replay-invariant).
__device__ __align__(16) int g_bins[(size_t)MAX_NOUT * CAP];  // 32 MB
__device__ int  g_cursor[MAX_NOUT];      // per-segment valid-edge count
__device__ int  g_ovf_cnt;
__device__ int2 g_ovf[OVF_CAP];          // {seg, tgt} overflow edges

// -------- kernel 1: fused validity + direct scatter (4 edges/thread) ------
// Stream inputs are read with .cs (read-once) so they do not evict the
// bins/cursor lines that k_pool reads right after this kernel.
__device__ __forceinline__ void scatter_one(int s, int tgt, int n_out) {
    if ((unsigned)s >= (unsigned)n_out) return;
    int p = atomicAdd(&g_cursor[s], 1);
    if (p < CAP) {
        g_bins[(size_t)s * CAP + p] = tgt;
    } else {
        int o = atomicAdd(&g_ovf_cnt, 1);
        if (o < OVF_CAP) g_ovf[o] = make_int2(s, tgt);
    }
}

__global__ void k_scatter_v4(const int4* __restrict__ src4,
                             const int4* __restrict__ tgt4,
                             const int4* __restrict__ nt4,
                             int E4, int n_out) {
    int t = blockIdx.x * blockDim.x + threadIdx.x;
    if (t >= E4) return;
    int4 n0 = __ldcs(&nt4[3 * t]);
    int4 n1 = __ldcs(&nt4[3 * t + 1]);
    int4 n2 = __ldcs(&nt4[3 * t + 2]);
    int4 s  = __ldcs(&src4[t]);
    int4 tg = __ldcs(&tgt4[t]);

    bool v0 = (n0.x >= 0) & (n0.y >= 0) & (n0.z >= 0);
    bool v1 = (n0.w >= 0) & (n1.x >= 0) & (n1.y >= 0);
    bool v2 = (n1.z >= 0) & (n1.w >= 0) & (n2.x >= 0);
    bool v3 = (n2.y >= 0) & (n2.z >= 0) & (n2.w >= 0);

    if (v0) scatter_one(s.x, tg.x, n_out);
    if (v1) scatter_one(s.y, tg.y, n_out);
    if (v2) scatter_one(s.z, tg.z, n_out);
    if (v3) scatter_one(s.w, tg.w, n_out);
}

// scalar fallback (odd shapes)
__global__ void k_scatter_s(const int* __restrict__ src_ids,
                            const int* __restrict__ tgt_ids,
                            const int* __restrict__ ntypes,
                            int E, int NT, int n_out) {
    int e = blockIdx.x * blockDim.x + threadIdx.x;
    if (e >= E) return;
    const int* nt = ntypes + (size_t)e * NT;
    bool valid = true;
    for (int j = 0; j < NT; j++) valid &= (nt[j] >= 0);
    if (valid) scatter_one(src_ids[e], tgt_ids[e], n_out);
}

// -------- kernel 2: pool. One segment per HALF-warp (2 segments/warp). ----
// 16 lanes x float4 cover the 64-ch row. Up to 8 feat rows in flight per
// half-warp (deg>=8 tier), falling through to 4/2/1. After reading the
// cursor, lane 0 of each half resets it to zero (same L2 line, ~free),
// restoring the pristine state for the next graph replay.
__global__ void k_pool(const float4* __restrict__ feat4,
                       float4* __restrict__ out4,
                       int n_out) {
    int warp  = (blockIdx.x * blockDim.x + threadIdx.x) >> 5;
    int lane  = threadIdx.x & 31;
    int half  = lane >> 4;
    int qlane = lane & 15;
    int seg   = warp * 2 + half;
    if (seg >= n_out) return;

    int cnt    = g_cursor[seg];
    if (qlane == 0) g_cursor[seg] = 0;    // self-reset for next replay
    int stored = cnt < CAP ? cnt : CAP;   // overflow handled post-pool
    const int* bins = g_bins + (size_t)seg * CAP;

    const float NI = -INFINITY;
    float4 acc = make_float4(NI, NI, NI, NI);

    int i = 0;
    for (; i + 7 < stored; i += 8) {
        int t0 = __ldg(&bins[i]);
        int t1 = __ldg(&bins[i + 1]);
        int t2 = __ldg(&bins[i + 2]);
        int t3 = __ldg(&bins[i + 3]);
        int t4 = __ldg(&bins[i + 4]);
        int t5 = __ldg(&bins[i + 5]);
        int t6 = __ldg(&bins[i + 6]);
        int t7 = __ldg(&bins[i + 7]);
        float4 a = __ldg(&feat4[(size_t)t0 * CV4 + qlane]);
        float4 b = __ldg(&feat4[(size_t)t1 * CV4 + qlane]);
        float4 c = __ldg(&feat4[(size_t)t2 * CV4 + qlane]);
        float4 d = __ldg(&feat4[(size_t)t3 * CV4 + qlane]);
        float4 e = __ldg(&feat4[(size_t)t4 * CV4 + qlane]);
        float4 f = __ldg(&feat4[(size_t)t5 * CV4 + qlane]);
        float4 g = __ldg(&feat4[(size_t)t6 * CV4 + qlane]);
        float4 h = __ldg(&feat4[(size_t)t7 * CV4 + qlane]);
        acc.x = fmaxf(acc.x, fmaxf(fmaxf(fmaxf(a.x, b.x), fmaxf(c.x, d.x)),
                                   fmaxf(fmaxf(e.x, f.x), fmaxf(g.x, h.x))));
        acc.y = fmaxf(acc.y, fmaxf(fmaxf(fmaxf(a.y, b.y), fmaxf(c.y, d.y)),
                                   fmaxf(fmaxf(e.y, f.y), fmaxf(g.y, h.y))));
        acc.z = fmaxf(acc.z, fmaxf(fmaxf(fmaxf(a.z, b.z), fmaxf(c.z, d.z)),
                                   fmaxf(fmaxf(e.z, f.z), fmaxf(g.z, h.z))));
        acc.w = fmaxf(acc.w, fmaxf(fmaxf(fmaxf(a.w, b.w), fmaxf(c.w, d.w)),
                                   fmaxf(fmaxf(e.w, f.w), fmaxf(g.w, h.w))));
    }
    for (; i + 3 < stored; i += 4) {
        int t0 = __ldg(&bins[i]);
        int t1 = __ldg(&bins[i + 1]);
        int t2 = __ldg(&bins[i + 2]);
        int t3 = __ldg(&bins[i + 3]);
        float4 a = __ldg(&feat4[(size_t)t0 * CV4 + qlane]);
        float4 b = __ldg(&feat4[(size_t)t1 * CV4 + qlane]);
        float4 c = __ldg(&feat4[(size_t)t2 * CV4 + qlane]);
        float4 d = __ldg(&feat4[(size_t)t3 * CV4 + qlane]);
        acc.x = fmaxf(fmaxf(fmaxf(acc.x, a.x), fmaxf(b.x, c.x)), d.x);
        acc.y = fmaxf(fmaxf(fmaxf(acc.y, a.y), fmaxf(b.y, c.y)), d.y);
        acc.z = fmaxf(fmaxf(fmaxf(acc.z, a.z), fmaxf(b.z, c.z)), d.z);
        acc.w = fmaxf(fmaxf(fmaxf(acc.w, a.w), fmaxf(b.w, c.w)), d.w);
    }
    for (; i + 1 < stored; i += 2) {
        int t0 = __ldg(&bins[i]);
        int t1 = __ldg(&bins[i + 1]);
        float4 a = __ldg(&feat4[(size_t)t0 * CV4 + qlane]);
        float4 b = __ldg(&feat4[(size_t)t1 * CV4 + qlane]);
        acc.x = fmaxf(acc.x, fmaxf(a.x, b.x));
        acc.y = fmaxf(acc.y, fmaxf(a.y, b.y));
        acc.z = fmaxf(acc.z, fmaxf(a.z, b.z));
        acc.w = fmaxf(acc.w, fmaxf(a.w, b.w));
    }
    if (i < stored) {
        int t0 = __ldg(&bins[i]);
        float4 a = __ldg(&feat4[(size_t)t0 * CV4 + qlane]);
        acc.x = fmaxf(acc.x, a.x);
        acc.y = fmaxf(acc.y, a.y);
        acc.z = fmaxf(acc.z, a.z);
        acc.w = fmaxf(acc.w, a.w);
    }

    if (cnt == 0) acc = make_float4(0.0f, 0.0f, 0.0f, 0.0f);
    __stcs(&out4[(size_t)seg * CV4 + qlane], acc);
}

// -------- kernel 3: resolve overflow, then reset its counter. -------------
// SINGLE block so the reset after __syncthreads() is race-free without an
// extra launch. Work is a few hundred entries (warp per entry, 32 warps).
__device__ __forceinline__ void atomicMaxFloat(float* addr, float val) {
    int* ia  = (int*)addr;
    int  old = *ia;
    while (__int_as_float(old) < val) {
        int assumed = old;
        old = atomicCAS(ia, assumed, __float_as_int(val));
        if (old == assumed) break;
    }
}

__global__ void k_overflow(const float* __restrict__ feat,
                           float* __restrict__ out, int n_out) {
    int n = g_ovf_cnt;
    if (n > OVF_CAP) n = OVF_CAP;
    int warps = blockDim.x >> 5;
    int w     = threadIdx.x >> 5;
    int lane  = threadIdx.x & 31;
    for (int k = w; k < n; k += warps) {
        int2 e = g_ovf[k];
        if ((unsigned)e.x >= (unsigned)n_out) continue;
        const float* row = feat + (size_t)e.y * CCH;
        float*       dst = out  + (size_t)e.x * CCH;
        #pragma unroll
        for (int c = lane; c < CCH; c += 32)
            atomicMaxFloat(&dst[c], row[c]);
    }
    __syncthreads();
    if (threadIdx.x == 0) g_ovf_cnt = 0;   // restore pristine state
}

// -------- optional tail: tuple's second element (feat_depth+1) --------
__global__ void k_tail(float* __restrict__ out, const int* __restrict__ feat_depth,
                       int begin, int total) {
    int i = begin + blockIdx.x * blockDim.x + threadIdx.x;
    if (i < total) out[i] = (float)(feat_depth[0] + 1);
}

extern "C" void kernel_launch(void* const* d_in, const int* in_sizes, int n_in,
                              void* d_out, int out_size) {
    const float* feat    = (const float*)d_in[0];
    const int*   src_ids = (const int*)  d_in[1];
    const int*   tgt_ids = (const int*)  d_in[2];
    const int*   ntypes  = (const int*)  d_in[3];

    int E  = in_sizes[1];
    int NT = (E > 0) ? in_sizes[3] / E : 3;
    if (E > MAX_E) E = MAX_E;
    if (NT < 1) NT = 1;

    int n_out = out_size / CCH;
    if (n_out > MAX_NOUT) n_out = MAX_NOUT;

    // 1. fused validity + direct scatter into fixed-capacity bins
    //    (cursors are guaranteed zero: static init on first call, pool
    //     self-reset on every subsequent call/replay)
    bool vec = (NT == 3) && (E % 4 == 0) &&
               ((((uintptr_t)src_ids | (uintptr_t)tgt_ids | (uintptr_t)ntypes) & 15u) == 0);
    if (vec) {
        int E4 = E / 4;
        k_scatter_v4<<<(E4 + 255) / 256, 256>>>((const int4*)src_ids,
                                                (const int4*)tgt_ids,
                                                (const int4*)ntypes, E4, n_out);
    } else {
        k_scatter_s<<<(E + 255) / 256, 256>>>(src_ids, tgt_ids, ntypes, E, NT, n_out);
    }

    // 2. pool: 2 segments per warp, 256 threads -> 16 segments per block
    int threads = 256;
    int segs_per_block = (threads / 32) * 2;
    int blocks = (n_out + segs_per_block - 1) / segs_per_block;
    k_pool<<<blocks, threads>>>((const float4*)feat, (float4*)d_out, n_out);

    // 3. resolve overflow entries + reset counter (single block)
    k_overflow<<<1, 1024>>>(feat, (float*)d_out, n_out);

    // tuple scalar tail (no-op for out_size == n_out*C)
    int main_elems = n_out * CCH;
    if (out_size > main_elems && n_in >= 6) {
        int extra = out_size - main_elems;
        k_tail<<<(extra + 255) / 256, 256>>>((float*)d_out, (const int*)d_in[5],
                                             main_elems, out_size);
    }
}

// round 16
// speedup vs baseline: 2.0833x; 2.0833x over previous
#include <cuda_runtime.h>
#include <math.h>
#include <stdint.h>

#define MAX_E     4194304
#define MAX_NOUT  524288
#define CCH       64            // channels
#define CV4       16            // float4 per row
#define CAP       16            // bin slots per segment (P(deg>16)~2e-4 -> overflow kernel)
#define OVF_CAP   262144

// -------- device scratch (no dynamic allocation allowed) --------
__device__ __align__(16) int g_bins[(size_t)MAX_NOUT * CAP];  // 32 MB
__device__ int  g_cursor[MAX_NOUT];      // per-segment valid-edge count
__device__ int  g_ovf_cnt;
__device__ int2 g_ovf[OVF_CAP];          // {seg, tgt} overflow edges

// -------- kernel 1: zero cursors --------
__global__ void k_zero(int n_out) {
    int i = blockIdx.x * blockDim.x + threadIdx.x;
    if (i < n_out) g_cursor[i] = 0;
    if (i == 0) g_ovf_cnt = 0;
}

// -------- kernel 2: fused validity + direct scatter (4 edges/thread) ------
// Stream inputs are read with .cs (read-once) so they do not evict the
// bins/cursor lines that k_pool reads right after this kernel.
__device__ __forceinline__ void scatter_one(int s, int tgt) {
    if ((unsigned)s >= (unsigned)MAX_NOUT) return;
    int p = atomicAdd(&g_cursor[s], 1);
    if (p < CAP) {
        g_bins[(size_t)s * CAP + p] = tgt;
    } else {
        int o = atomicAdd(&g_ovf_cnt, 1);
        if (o < OVF_CAP) g_ovf[o] = make_int2(s, tgt);
    }
}

__global__ void k_scatter_v4(const int4* __restrict__ src4,
                             const int4* __restrict__ tgt4,
                             const int4* __restrict__ nt4,
                             int E4) {
    int t = blockIdx.x * blockDim.x + threadIdx.x;
    if (t >= E4) return;
    int4 n0 = __ldcs(&nt4[3 * t]);
    int4 n1 = __ldcs(&nt4[3 * t + 1]);
    int4 n2 = __ldcs(&nt4[3 * t + 2]);
    int4 s  = __ldcs(&src4[t]);
    int4 tg = __ldcs(&tgt4[t]);

    bool v0 = (n0.x >= 0) & (n0.y >= 0) & (n0.z >= 0);
    bool v1 = (n0.w >= 0) & (n1.x >= 0) & (n1.y >= 0);
    bool v2 = (n1.z >= 0) & (n1.w >= 0) & (n2.x >= 0);
    bool v3 = (n2.y >= 0) & (n2.z >= 0) & (n2.w >= 0);

    if (v0) scatter_one(s.x, tg.x);
    if (v1) scatter_one(s.y, tg.y);
    if (v2) scatter_one(s.z, tg.z);
    if (v3) scatter_one(s.w, tg.w);
}

// scalar fallback (odd shapes)
__global__ void k_scatter_s(const int* __restrict__ src_ids,
                            const int* __restrict__ tgt_ids,
                            const int* __restrict__ ntypes,
                            int E, int NT) {
    int e = blockIdx.x * blockDim.x + threadIdx.x;
    if (e >= E) return;
    const int* nt = ntypes + (size_t)e * NT;
    bool valid = true;
    for (int j = 0; j < NT; j++) valid &= (nt[j] >= 0);
    if (valid) scatter_one(src_ids[e], tgt_ids[e]);
}

// -------- kernel 3: pool. One segment per HALF-warp (2 segments/warp). ----
// 16 lanes x float4 cover the 64-ch row. Up to 8 feat rows in flight per
// half-warp (deg>=8 tier), falling through to 4/2/1. bins reads default-
// cached (expected L2-resident from scatter); output written with .cs.
__global__ void k_pool(const float4* __restrict__ feat4,
                       float4* __restrict__ out4,
                       int n_out) {
    int warp  = (blockIdx.x * blockDim.x + threadIdx.x) >> 5;
    int lane  = threadIdx.x & 31;
    int half  = lane >> 4;
    int qlane = lane & 15;
    int seg   = warp * 2 + half;
    if (seg >= n_out) return;

    int cnt    = g_cursor[seg];
    int stored = cnt < CAP ? cnt : CAP;   // overflow handled post-pool
    const int* bins = g_bins + (size_t)seg * CAP;

    const float NI = -INFINITY;
    float4 acc = make_float4(NI, NI, NI, NI);

    int i = 0;
    for (; i + 7 < stored; i += 8) {
        int t0 = __ldg(&bins[i]);
        int t1 = __ldg(&bins[i + 1]);
        int t2 = __ldg(&bins[i + 2]);
        int t3 = __ldg(&bins[i + 3]);
        int t4 = __ldg(&bins[i + 4]);
        int t5 = __ldg(&bins[i + 5]);
        int t6 = __ldg(&bins[i + 6]);
        int t7 = __ldg(&bins[i + 7]);
        float4 a = __ldg(&feat4[(size_t)t0 * CV4 + qlane]);
        float4 b = __ldg(&feat4[(size_t)t1 * CV4 + qlane]);
        float4 c = __ldg(&feat4[(size_t)t2 * CV4 + qlane]);
        float4 d = __ldg(&feat4[(size_t)t3 * CV4 + qlane]);
        float4 e = __ldg(&feat4[(size_t)t4 * CV4 + qlane]);
        float4 f = __ldg(&feat4[(size_t)t5 * CV4 + qlane]);
        float4 g = __ldg(&feat4[(size_t)t6 * CV4 + qlane]);
        float4 h = __ldg(&feat4[(size_t)t7 * CV4 + qlane]);
        acc.x = fmaxf(acc.x, fmaxf(fmaxf(fmaxf(a.x, b.x), fmaxf(c.x, d.x)),
                                   fmaxf(fmaxf(e.x, f.x), fmaxf(g.x, h.x))));
        acc.y = fmaxf(acc.y, fmaxf(fmaxf(fmaxf(a.y, b.y), fmaxf(c.y, d.y)),
                                   fmaxf(fmaxf(e.y, f.y), fmaxf(g.y, h.y))));
        acc.z = fmaxf(acc.z, fmaxf(fmaxf(fmaxf(a.z, b.z), fmaxf(c.z, d.z)),
                                   fmaxf(fmaxf(e.z, f.z), fmaxf(g.z, h.z))));
        acc.w = fmaxf(acc.w, fmaxf(fmaxf(fmaxf(a.w, b.w), fmaxf(c.w, d.w)),
                                   fmaxf(fmaxf(e.w, f.w), fmaxf(g.w, h.w))));
    }
    for (; i + 3 < stored; i += 4) {
        int t0 = __ldg(&bins[i]);
        int t1 = __ldg(&bins[i + 1]);
        int t2 = __ldg(&bins[i + 2]);
        int t3 = __ldg(&bins[i + 3]);
        float4 a = __ldg(&feat4[(size_t)t0 * CV4 + qlane]);
        float4 b = __ldg(&feat4[(size_t)t1 * CV4 + qlane]);
        float4 c = __ldg(&feat4[(size_t)t2 * CV4 + qlane]);
        float4 d = __ldg(&feat4[(size_t)t3 * CV4 + qlane]);
        acc.x = fmaxf(fmaxf(fmaxf(acc.x, a.x), fmaxf(b.x, c.x)), d.x);
        acc.y = fmaxf(fmaxf(fmaxf(acc.y, a.y), fmaxf(b.y, c.y)), d.y);
        acc.z = fmaxf(fmaxf(fmaxf(acc.z, a.z), fmaxf(b.z, c.z)), d.z);
        acc.w = fmaxf(fmaxf(fmaxf(acc.w, a.w), fmaxf(b.w, c.w)), d.w);
    }
    for (; i + 1 < stored; i += 2) {
        int t0 = __ldg(&bins[i]);
        int t1 = __ldg(&bins[i + 1]);
        float4 a = __ldg(&feat4[(size_t)t0 * CV4 + qlane]);
        float4 b = __ldg(&feat4[(size_t)t1 * CV4 + qlane]);
        acc.x = fmaxf(acc.x, fmaxf(a.x, b.x));
        acc.y = fmaxf(acc.y, fmaxf(a.y, b.y));
        acc.z = fmaxf(acc.z, fmaxf(a.z, b.z));
        acc.w = fmaxf(acc.w, fmaxf(a.w, b.w));
    }
    if (i < stored) {
        int t0 = __ldg(&bins[i]);
        float4 a = __ldg(&feat4[(size_t)t0 * CV4 + qlane]);
        acc.x = fmaxf(acc.x, a.x);
        acc.y = fmaxf(acc.y, a.y);
        acc.z = fmaxf(acc.z, a.z);
        acc.w = fmaxf(acc.w, a.w);
    }

    if (cnt == 0) acc = make_float4(0.0f, 0.0f, 0.0f, 0.0f);
    __stcs(&out4[(size_t)seg * CV4 + qlane], acc);
}

// -------- kernel 4: resolve overflow (few hundred entries at CAP=16) ------
__device__ __forceinline__ void atomicMaxFloat(float* addr, float val) {
    int* ia  = (int*)addr;
    int  old = *ia;
    while (__int_as_float(old) < val) {
        int assumed = old;
        old = atomicCAS(ia, assumed, __float_as_int(val));
        if (old == assumed) break;
    }
}

__global__ void k_overflow(const float* __restrict__ feat,
                           float* __restrict__ out, int n_out) {
    int n = g_ovf_cnt;
    if (n > OVF_CAP) n = OVF_CAP;
    if (n == 0) return;
    int warps = (gridDim.x * blockDim.x) >> 5;
    int w     = (blockIdx.x * blockDim.x + threadIdx.x) >> 5;
    int lane  = threadIdx.x & 31;
    for (int k = w; k < n; k += warps) {
        int2 e = g_ovf[k];
        if ((unsigned)e.x >= (unsigned)n_out) continue;
        const float* row = feat + (size_t)e.y * CCH;
        float*       dst = out  + (size_t)e.x * CCH;
        #pragma unroll
        for (int c = lane; c < CCH; c += 32)
            atomicMaxFloat(&dst[c], row[c]);
    }
}

// -------- optional tail: tuple's second element (feat_depth+1) --------
__global__ void k_tail(float* __restrict__ out, const int* __restrict__ feat_depth,
                       int begin, int total) {
    int i = begin + blockIdx.x * blockDim.x + threadIdx.x;
    if (i < total) out[i] = (float)(feat_depth[0] + 1);
}

extern "C" void kernel_launch(void* const* d_in, const int* in_sizes, int n_in,
                              void* d_out, int out_size) {
    const float* feat    = (const float*)d_in[0];
    const int*   src_ids = (const int*)  d_in[1];
    const int*   tgt_ids = (const int*)  d_in[2];
    const int*   ntypes  = (const int*)  d_in[3];

    int E  = in_sizes[1];
    int NT = (E > 0) ? in_sizes[3] / E : 3;
    if (E > MAX_E) E = MAX_E;
    if (NT < 1) NT = 1;

    int n_out = out_size / CCH;
    if (n_out > MAX_NOUT) n_out = MAX_NOUT;

    // 1. zero cursors
    k_zero<<<(n_out + 255) / 256, 256>>>(n_out);

    // 2. fused validity + direct scatter into fixed-capacity bins
    bool vec = (NT == 3) && (E % 4 == 0) &&
               ((((uintptr_t)src_ids | (uintptr_t)tgt_ids | (uintptr_t)ntypes) & 15u) == 0);
    if (vec) {
        int E4 = E / 4;
        k_scatter_v4<<<(E4 + 255) / 256, 256>>>((const int4*)src_ids,
                                                (const int4*)tgt_ids,
                                                (const int4*)ntypes, E4);
    } else {
        k_scatter_s<<<(E + 255) / 256, 256>>>(src_ids, tgt_ids, ntypes, E, NT);
    }

    // 3. pool: 2 segments per warp, 256 threads -> 16 segments per block
    int threads = 256;
    int segs_per_block = (threads / 32) * 2;
    int blocks = (n_out + segs_per_block - 1) / segs_per_block;
    k_pool<<<blocks, threads>>>((const float4*)feat, (float4*)d_out, n_out);

    // 4. resolve overflow entries (hundreds at CAP=16; warp per entry)
    k_overflow<<<16, 256>>>(feat, (float*)d_out, n_out);

    // tuple scalar tail (no-op for out_size == n_out*C)
    int main_elems = n_out * CCH;
    if (out_size > main_elems && n_in >= 6) {
        int extra = out_size - main_elems;
        k_tail<<<(extra + 255) / 256, 256>>>((float*)d_out, (const int*)d_in[5],
                                             main_elems, out_size);
    }
}